// round 2
// baseline (speedup 1.0000x reference)
#include <cuda_runtime.h>

// inputs: float32 [16, 64, 256, 256] NCHW
#define NB        16
#define NC        64
#define HW4       16384              // float4 per (n,c) slice
#define CHUNKS    64                 // reduce chunks over hw4
#define TPB       256
#define PERCHAN4  (NB * HW4)         // 262144 float4 per channel
#define TOTAL4    (NB * NC * HW4)    // 16,777,216 float4
#define EPS       1e-5f

// Deterministic partials: written unconditionally every call, no zeroing needed.
__device__ float g_psum[NC * CHUNKS];
__device__ float g_psq [NC * CHUNKS];
__device__ float g_mean[NC];
__device__ float g_rstd[NC];

// grid = (NC, CHUNKS): blockIdx.x = channel (fastest-varying -> block waves
// sweep hw4-major across all channels), blockIdx.y = hw4 chunk.
// Each thread: 16 fully-unrolled independent float4 loads (one per n).
__global__ void reduce_kernel(const float4* __restrict__ in) {
    const int c       = blockIdx.x;
    const int tglob   = blockIdx.y * TPB + threadIdx.x;     // hw4 index [0,16384)
    const float4* p   = in + (size_t)c * HW4 + tglob;       // n=0 element

    float4 v[NB];
    #pragma unroll
    for (int n = 0; n < NB; n++)
        v[n] = __ldcg(&p[(size_t)n * NC * HW4]);

    float s = 0.0f, q = 0.0f;
    #pragma unroll
    for (int n = 0; n < NB; n++) {
        s += (v[n].x + v[n].y) + (v[n].z + v[n].w);
        q += (v[n].x * v[n].x + v[n].y * v[n].y)
           + (v[n].z * v[n].z + v[n].w * v[n].w);
    }

    // warp reduce
    #pragma unroll
    for (int off = 16; off > 0; off >>= 1) {
        s += __shfl_down_sync(0xffffffffu, s, off);
        q += __shfl_down_sync(0xffffffffu, q, off);
    }

    __shared__ float sh_s[8], sh_q[8];
    const int lane = threadIdx.x & 31;
    const int wid  = threadIdx.x >> 5;
    if (lane == 0) { sh_s[wid] = s; sh_q[wid] = q; }
    __syncthreads();

    if (wid == 0) {
        s = (lane < (TPB >> 5)) ? sh_s[lane] : 0.0f;
        q = (lane < (TPB >> 5)) ? sh_q[lane] : 0.0f;
        #pragma unroll
        for (int off = 4; off > 0; off >>= 1) {
            s += __shfl_down_sync(0xffffffffu, s, off);
            q += __shfl_down_sync(0xffffffffu, q, off);
        }
        if (lane == 0) {
            g_psum[c * CHUNKS + blockIdx.y] = s;
            g_psq [c * CHUNKS + blockIdx.y] = q;
        }
    }
}

// 64 threads: each folds its channel's 64 partials.
__global__ void finalize_kernel() {
    const int c = threadIdx.x;
    float s = 0.0f, q = 0.0f;
    #pragma unroll
    for (int k = 0; k < CHUNKS; k++) {
        s += g_psum[c * CHUNKS + k];
        q += g_psq [c * CHUNKS + k];
    }
    const float invN = 1.0f / (float)(PERCHAN4 * 4);
    const float mean = s * invN;
    g_mean[c] = mean;
    g_rstd[c] = rsqrtf(q * invN - mean * mean + EPS);
}

// 16384 blocks, each covers 1024 contiguous float4 (16 KB) within one slice.
// Block order: hw-segment DESCENDING major, slice minor -> the first waves
// read exactly the hw4 region the reduce pass touched last (L2 residual hits).
// __ldcs / __stcs: evict-first so output stores don't flush useful input lines.
__global__ void normalize_kernel(const float4* __restrict__ in,
                                 float4* __restrict__ out) {
    const int b     = blockIdx.x;
    const int hseg  = 15 - (b >> 10);         // [15..0], 1024 float4 each
    const int slice = b & 1023;               // n*NC + c
    const int c     = slice & (NC - 1);

    const float mean = g_mean[c];
    const float rstd = g_rstd[c];

    const size_t base = (size_t)slice * HW4 + (size_t)hseg * 1024 + threadIdx.x;

    #pragma unroll
    for (int k = 0; k < 4; k++) {
        const size_t idx = base + k * TPB;
        float4 v = __ldcs(&in[idx]);
        float4 o;
        o.x = (v.x - mean) * rstd;
        o.y = (v.y - mean) * rstd;
        o.z = (v.z - mean) * rstd;
        o.w = (v.w - mean) * rstd;
        __stcs(&out[idx], o);
    }
}

extern "C" void kernel_launch(void* const* d_in, const int* in_sizes, int n_in,
                              void* d_out, int out_size) {
    const float4* in  = (const float4*)d_in[0];
    float4*       out = (float4*)d_out;

    dim3 rgrid(NC, CHUNKS);            // x = channel (fastest), y = hw4 chunk
    reduce_kernel<<<rgrid, TPB>>>(in);
    finalize_kernel<<<1, NC>>>();
    normalize_kernel<<<TOTAL4 / (TPB * 4), TPB>>>(in, out);
}